// round 12
// baseline (speedup 1.0000x reference)
#include <cuda_runtime.h>
#include <math.h>

#define G     15
#define NB    4
#define NPTS  300000
#define PPC   (NB*NPTS)

// padded grid: [B][12][19 planes][19 rows][24 cols]
#define PLANE 456
#define CSTR  8672
#define BSTR  (12*CSTR)
#define GRIDN (NB*BSTR)

typedef unsigned long long ull;

__device__ float  g_grid[GRIDN];
__device__ float  g_bufA[NB*8*512];
__device__ float  g_bufB[NB*8*512];
__device__ float2 g_slots0[128];
__device__ float2 g_slots1[128];
__device__ unsigned g_flags[128];
__device__ unsigned g_phasev = 0;

// ---------------- helpers ---------------------------------------------------
__device__ __forceinline__ ull pack2(float lo, float hi){
    ull r; asm("mov.b64 %0, {%1,%2};" : "=l"(r) : "f"(lo), "f"(hi)); return r;
}
__device__ __forceinline__ void unpack2(ull v, float& lo, float& hi){
    asm("mov.b64 {%0,%1}, %2;" : "=f"(lo), "=f"(hi) : "l"(v));
}
__device__ __forceinline__ ull fma2(ull a, ull b, ull c){
    ull d; asm("fma.rn.f32x2 %0, %1, %2, %3;" : "=l"(d) : "l"(a), "l"(b), "l"(c)); return d;
}
__device__ __forceinline__ float eluf(float x){ return x > 0.f ? x : (__expf(x)-1.f); }
__device__ __forceinline__ ull elu2(ull v){
    float lo, hi; unpack2(v, lo, hi);
    return pack2(eluf(lo), eluf(hi));
}

// flag-based grid barrier (block0 parallel detect + phase release; monotonic)
__device__ __forceinline__ void gridBar(int t, int bid){
    __shared__ unsigned sMy;
    __syncthreads();
    __threadfence();
    if (t==0) sMy = *((volatile unsigned*)&g_phasev);
    __syncthreads();
    unsigned nxt = sMy + 1u;
    if (bid == 0){
        if (t < 127){
            while (((volatile unsigned*)g_flags)[t+1] != nxt) { }
        }
        __syncthreads();
        __threadfence();
        if (t==0) *((volatile unsigned*)&g_phasev) = nxt;
    } else {
        if (t==0){
            ((volatile unsigned*)g_flags)[bid] = nxt;
            while (*((volatile unsigned*)&g_phasev) != nxt) { }
        }
    }
    __syncthreads();
    __threadfence();
}

// two-value reduction over 384 threads (12 warps)
__device__ __forceinline__ float2 blockRed2(float a, float b, float* sm, int t){
    #pragma unroll
    for (int o=16;o;o>>=1){
        a += __shfl_xor_sync(0xffffffffu, a, o);
        b += __shfl_xor_sync(0xffffffffu, b, o);
    }
    if ((t&31)==0){ sm[(t>>5)*2]=a; sm[(t>>5)*2+1]=b; }
    __syncthreads();
    float2 r; r.x=0.f; r.y=0.f;
    #pragma unroll
    for (int wq=0;wq<12;wq++){ r.x += sm[wq*2]; r.y += sm[wq*2+1]; }
    return r;
}

// ---------------- point stage: 2 pts/thread, channel-pair packed f32x2 ------
__device__ __forceinline__ void disty6(float px, float py, float pz,
                                       float f[6], int& cellpad)
{
    const float CLIPHI = 15.0f - 1e-4f;
    float cx = floorf(fminf(fmaxf(px,0.f), CLIPHI));
    float cy = floorf(fminf(fmaxf(py,0.f), CLIPHI));
    float cz = floorf(fminf(fmaxf(pz,0.f), CLIPHI));
    float ocx = px-cx-0.5f, ocy = py-cy-0.5f, ocz = pz-cz-0.5f;
    float lx = ocx+0.5f, ly = ocy+0.5f, lz = ocz+0.5f;
    float ux = ocx-0.5f, uy = ocy-0.5f, uz = ocz-0.5f;
    f[0]=ocx; f[1]=ocy; f[2]=ocz;
    f[3] = sqrtf(ocx*ocx+ocy*ocy+ocz*ocz);
    f[4] = sqrtf(lx*lx+ly*ly+lz*lz);
    f[5] = sqrtf(ux*ux+uy*uy+uz*uz);
    cellpad = ((int)cx+2)*PLANE + ((int)cy+2)*24 + ((int)cz+2);
}

__device__ __forceinline__ void mlp_point(const float f[6], int cell, int b, int chan,
                                          const ull* pW1, const ull* pW2, const ull* pW3,
                                          const ull* pb1, const ull* pb2, const ull* pb3)
{
    ull h[8];
    {
        ull xx0=pack2(f[0],f[0]), xx1=pack2(f[1],f[1]), xx2=pack2(f[2],f[2]);
        ull xx3=pack2(f[3],f[3]), xx4=pack2(f[4],f[4]), xx5=pack2(f[5],f[5]);
        #pragma unroll
        for (int jp=0;jp<8;jp++){
            ull a = pb1[jp];
            a = fma2(xx0, pW1[0*8+jp], a);
            a = fma2(xx1, pW1[1*8+jp], a);
            a = fma2(xx2, pW1[2*8+jp], a);
            a = fma2(xx3, pW1[3*8+jp], a);
            a = fma2(xx4, pW1[4*8+jp], a);
            a = fma2(xx5, pW1[5*8+jp], a);
            h[jp] = elu2(a);
        }
    }
    ull hh[16];
    #pragma unroll
    for (int jp=0;jp<8;jp++){
        float s0, s1; unpack2(h[jp], s0, s1);
        hh[2*jp]   = pack2(s0, s0);
        hh[2*jp+1] = pack2(s1, s1);
    }
    ull g[8];
    #pragma unroll
    for (int jp=0;jp<8;jp++){
        ull a = pb2[jp];
        #pragma unroll
        for (int k=0;k<16;k++) a = fma2(hh[k], pW2[k*8+jp], a);
        g[jp] = elu2(a);
    }
    #pragma unroll
    for (int jp=0;jp<8;jp++){
        float s0, s1; unpack2(g[jp], s0, s1);
        hh[2*jp]   = pack2(s0, s0);
        hh[2*jp+1] = pack2(s1, s1);
    }
    int base = b*BSTR + chan*CSTR + cell;
    #pragma unroll
    for (int jp=0;jp<2;jp++){
        ull a = pb3[jp];
        #pragma unroll
        for (int k=0;k<16;k++) a = fma2(hh[k], pW3[k*2+jp], a);
        float v0, v1; unpack2(a, v0, v1);
        if (v0 > 0.f) atomicMax((int*)&g_grid[base + (2*jp  )*CSTR], __float_as_int(v0));
        if (v1 > 0.f) atomicMax((int*)&g_grid[base + (2*jp+1)*CSTR], __float_as_int(v1));
    }
}

__global__ void __launch_bounds__(256,3)
point_kernel(const float* __restrict__ P0, const float* __restrict__ P1,
             const float* __restrict__ P2,
             const float* __restrict__ W1, const float* __restrict__ B1,
             const float* __restrict__ W2, const float* __restrict__ B2,
             const float* __restrict__ W3, const float* __restrict__ B3)
{
    __shared__ __align__(16) ull pW1[48], pW2[128], pW3[32];
    __shared__ ull pb1[8], pb2[8], pb3[2];
    int t = threadIdx.x;

    if (t < 48){
        int k = t>>3, jp = t&7, j0 = 2*jp, j1 = 2*jp+1;
        float w0, w1v;
        if (k < 3){
            w0  = W1[k*16+j0]+W1[(k+3)*16+j0]+W1[(k+6)*16+j0];
            w1v = W1[k*16+j1]+W1[(k+3)*16+j1]+W1[(k+6)*16+j1];
        } else {
            w0  = W1[(k+6)*16+j0];
            w1v = W1[(k+6)*16+j1];
        }
        pW1[k*8+jp] = pack2(w0, w1v);
    }
    if (t < 8){
        int j0 = 2*t, j1 = 2*t+1;
        float be0 = B1[j0] + 0.5f*((W1[3*16+j0]+W1[4*16+j0]+W1[5*16+j0])
                                 - (W1[6*16+j0]+W1[7*16+j0]+W1[8*16+j0]));
        float be1 = B1[j1] + 0.5f*((W1[3*16+j1]+W1[4*16+j1]+W1[5*16+j1])
                                 - (W1[6*16+j1]+W1[7*16+j1]+W1[8*16+j1]));
        pb1[t] = pack2(be0, be1);
        pb2[t] = pack2(B2[j0], B2[j1]);
    }
    if (t < 128){
        int k = t>>3, jp = t&7;
        pW2[k*8+jp] = pack2(W2[k*16+2*jp], W2[k*16+2*jp+1]);
    }
    if (t < 32){
        int k = t>>1, jp = t&1;
        pW3[k*2+jp] = pack2(W3[k*4+2*jp], W3[k*4+2*jp+1]);
    }
    if (t < 2) pb3[t] = pack2(B3[2*t], B3[2*t+1]);
    __syncthreads();

    const float* pts = (blockIdx.y==0) ? P0 : (blockIdx.y==1 ? P1 : P2);
    int chan = blockIdx.y*4;

    long p0 = ((long)blockIdx.x*256 + t)*2;
    if (p0 >= PPC) return;

    // two consecutive points: 6 floats via 3 aligned float2
    const float2* v = (const float2*)(pts + p0*3);
    float2 q0=v[0], q1=v[1], q2=v[2];
    int b = (int)(p0 / NPTS);

    {
        float fa[6]; int ca;
        disty6(q0.x, q0.y, q1.x, fa, ca);
        mlp_point(fa, ca, b, chan, pW1, pW2, pW3, pb1, pb2, pb3);
    }
    {
        float fb[6]; int cb;
        disty6(q1.y, q2.x, q2.y, fb, cb);
        mlp_point(fb, cb, b, chan, pW1, pW2, pW3, pb1, pb2, pb3);
    }
}

// ---------------- fused conv stack: 384 threads/block -----------------------
// grid 128 = (oc8, b4, odp4); thread = (cic, odl, oh, owh) computes 4 ow.
// Weights double-buffered: layer L+1 prefetched during layer L's epilogue.
__global__ void __launch_bounds__(384,1)
conv_stack_kernel(const float* __restrict__ w1,
                  const float* __restrict__ wS,
                  const float* __restrict__ bn1_g, const float* __restrict__ bn1_b,
                  const float* __restrict__ bns_g, const float* __restrict__ bns_b,
                  float* __restrict__ outp)
{
    __shared__ __align__(16) float sIn[6912];    // [8 ic][6 dd][12 h][12 w]
    __shared__ __align__(16) float wsm[3200];    // 2 x [8 ic][5 kd][5 kh][8 pad]
    __shared__ __align__(16) float sAcc[1536];   // [<=12 ic][128 out]
    __shared__ float sSc[8], sSh[8], sred[24];

    int bid = blockIdx.x;
    int oc = bid & 7, b = (bid>>3) & 3, odp = bid>>5;
    int t = threadIdx.x;
    int owh  = t&1;
    int coh  = (t>>1)&7;
    int codl = (t>>4)&1;
    int cic  = t>>5;
    int obase = b*4096 + oc*512 + odp*128;

    { // zero sIn once (halo cells identical every layer)
        float4 z4 = make_float4(0.f,0.f,0.f,0.f);
        for (int i=t;i<1728;i+=384) ((float4*)sIn)[i] = z4;
    }

    // prefetch L=0 weights into buffer 0 (overlaps conv1 compute)
    for (int i=t;i<1000;i+=384){
        int ic=i/125, r=i%125, kd=r/25, kh=(r%25)/5, kw=r%5;
        wsm[((ic*5+kd)*5+kh)*8 + kw] = wS[oc*1000 + i];
    }

    // ================= conv1: 12->8, k5, s2, p2, direct-from-L2 =============
    float accL;
    {
        float a[4] = {0.f,0.f,0.f,0.f};
        const float* gch = g_grid + (b*12+cic)*CSTR;
        const float* wp0 = w1 + (oc*12+cic)*125;
        int od = odp*2 + codl;
        #pragma unroll
        for (int kd=0;kd<5;kd++){
            #pragma unroll
            for (int kh=0;kh<5;kh++){
                const float* row = gch + (2*od+kd)*PLANE + (2*coh+kh)*24 + 8*owh;
                float4 r0 = *(const float4*)(row);
                float4 r1 = *(const float4*)(row+4);
                float4 r2 = *(const float4*)(row+8);
                float rr[12] = {r0.x,r0.y,r0.z,r0.w, r1.x,r1.y,r1.z,r1.w,
                                r2.x,r2.y,r2.z,r2.w};
                const float* wp = wp0 + kd*25 + kh*5;
                float wk0=__ldg(wp), wk1=__ldg(wp+1), wk2=__ldg(wp+2),
                      wk3=__ldg(wp+3), wk4=__ldg(wp+4);
                #pragma unroll
                for (int o=0;o<4;o++){
                    a[o] += rr[2*o+0]*wk0;
                    a[o] += rr[2*o+1]*wk1;
                    a[o] += rr[2*o+2]*wk2;
                    a[o] += rr[2*o+3]*wk3;
                    a[o] += rr[2*o+4]*wk4;
                }
            }
        }
        int oidx = codl*64 + coh*8 + owh*4;
        #pragma unroll
        for (int o=0;o<4;o++) sAcc[cic*128 + oidx + o] = a[o];
        __syncthreads();

        float s = 0.f;
        if (t < 128){
            #pragma unroll
            for (int ic=0;ic<12;ic++) s += sAcc[ic*128 + t];
            __stcg(&g_bufA[obase + t], s);
        }
        accL = s;
        float2 r = blockRed2(t<128 ? s : 0.f, t<128 ? s*s : 0.f, sred, t);
        if (t==0){ g_slots0[oc*16 + b*4 + odp] = r; }
    }
    gridBar(t, bid);

    // ================= 6x (input BN+ELU -> conv 8->8 k5 p2) =================
    for (int L=0; L<6; L++){
        int dir = L & 1;
        const float*  rin  = dir ? g_bufB   : g_bufA;
        float*        rout = dir ? g_bufA   : g_bufB;
        const float2* sinp = dir ? g_slots1 : g_slots0;
        float2*       sout = dir ? g_slots0 : g_slots1;
        const float*  gin  = (L==0) ? bn1_g : (bns_g + (L-1)*8);
        const float*  bin  = (L==0) ? bn1_b : (bns_b + (L-1)*8);
        const float*  wcur = wsm + (L&1)*1600;

        if (t < 8){
            float sx=0.f, sy=0.f;
            #pragma unroll
            for (int q=0;q<16;q++){
                float2 p = *(const float2*)&sinp[t*16+q];
                sx+=p.x; sy+=p.y;
            }
            float m  = sx*(1.f/2048.f);
            float vr = sy*(1.f/2048.f) - m*m;
            float sc = gin[t]*rsqrtf(vr + 1e-5f);
            sSc[t]=sc; sSh[t]=bin[t]-m*sc;
        }
        __syncthreads();

        // batched interior fill (768 float4 items over 384 threads)
        {
            float4 vv[2]; bool ok[2]; int di[2];
            #pragma unroll
            for (int u=0;u<2;u++){
                int i = t + u*384;
                int half = i&1, h = (i>>1)&7, dd = (i>>4)%6, ic = i/96;
                int id = odp*2 - 2 + dd;
                ok[u] = (unsigned)id < 8u;
                di[u] = ic*864 + dd*144 + (h+2)*12 + 2 + half*4;
                if (ok[u])
                    vv[u] = __ldcg((const float4*)(rin + b*4096 + ic*512 + id*64 + h*8 + half*4));
            }
            #pragma unroll
            for (int u=0;u<2;u++){
                if (ok[u]){
                    int i = t + u*384;
                    int ic = i/96;
                    float sc = sSc[ic], sh = sSh[ic];
                    float* d = sIn + di[u];
                    d[0]=eluf(vv[u].x*sc+sh); d[1]=eluf(vv[u].y*sc+sh);
                    d[2]=eluf(vv[u].z*sc+sh); d[3]=eluf(vv[u].w*sc+sh);
                }
            }
        }
        __syncthreads();

        float a[4] = {0.f,0.f,0.f,0.f};
        if (cic < 8){
            const float* cb = sIn + cic*864;
            const float* wb = wcur + cic*200;
            #pragma unroll
            for (int kd=0;kd<5;kd++){
                #pragma unroll
                for (int kh=0;kh<5;kh++){
                    const float* row = cb + (codl+kd)*144 + (coh+kh)*12 + owh*4;
                    float4 r0 = *(const float4*)(row);
                    float4 r1 = *(const float4*)(row+4);
                    float rr[8] = {r0.x,r0.y,r0.z,r0.w, r1.x,r1.y,r1.z,r1.w};
                    const float* wp = wb + (kd*5+kh)*8;
                    float4 wv = *(const float4*)wp;
                    float wk4 = wp[4];
                    #pragma unroll
                    for (int o=0;o<4;o++){
                        a[o] += rr[o+0]*wv.x;
                        a[o] += rr[o+1]*wv.y;
                        a[o] += rr[o+2]*wv.z;
                        a[o] += rr[o+3]*wv.w;
                        a[o] += rr[o+4]*wk4;
                    }
                }
            }
            int oidx = codl*64 + coh*8 + owh*4;
            #pragma unroll
            for (int o=0;o<4;o++) sAcc[cic*128 + oidx + o] = a[o];
        }
        __syncthreads();

        // prefetch next layer's weights into the other buffer (overlaps epilogue)
        if (L < 5){
            float* wn = wsm + ((L+1)&1)*1600;
            const float* wsrc = wS + (L+1)*8000 + oc*1000;
            for (int i=t;i<1000;i+=384){
                int ic=i/125, r=i%125, kd=r/25, kh=(r%25)/5, kw=r%5;
                wn[((ic*5+kd)*5+kh)*8 + kw] = wsrc[i];
            }
        }

        float s = 0.f;
        if (t < 128){
            #pragma unroll
            for (int ic=0;ic<8;ic++) s += sAcc[ic*128 + t];
            __stcg(&rout[obase + t], s);
        }
        accL = s;
        float2 r = blockRed2(t<128 ? s : 0.f, t<128 ? s*s : 0.f, sred, t);
        if (t==0){ sout[oc*16 + b*4 + odp] = r; }
        gridBar(t, bid);
    }

    // ================= final BN+ELU from live accumulator ===================
    if (t < 128){
        float sx=0.f, sy=0.f;
        #pragma unroll
        for (int q=0;q<16;q++){
            float2 p = *(const float2*)&g_slots0[oc*16+q];
            sx+=p.x; sy+=p.y;
        }
        float m  = sx*(1.f/2048.f);
        float vr = sy*(1.f/2048.f) - m*m;
        float sc = bns_g[40+oc]*rsqrtf(vr + 1e-5f);
        float sh = bns_b[40+oc]-m*sc;
        outp[(b*8+oc)*512 + odp*128 + t] = eluf(accL*sc+sh);
    }
}

// ---------------------------------------------------------------------------
extern "C" void kernel_launch(void* const* d_in, const int* in_sizes, int n_in,
                              void* d_out, int out_size)
{
    const float* goals       = (const float*)d_in[0];
    const float* inputs      = (const float*)d_in[1];
    const float* backgrounds = (const float*)d_in[2];
    const float* W1 = (const float*)d_in[3];
    const float* b1 = (const float*)d_in[4];
    const float* W2 = (const float*)d_in[5];
    const float* b2 = (const float*)d_in[6];
    const float* W3 = (const float*)d_in[7];
    const float* b3 = (const float*)d_in[8];
    const float* conv1_w = (const float*)d_in[9];
    const float* bn1_g   = (const float*)d_in[11];
    const float* bn1_b   = (const float*)d_in[12];
    const float* convs_w = (const float*)d_in[13];
    const float* bns_g   = (const float*)d_in[15];
    const float* bns_b   = (const float*)d_in[16];
    float* out = (float*)d_out;

    void* gptr = nullptr;
    cudaGetSymbolAddress(&gptr, g_grid);
    cudaMemsetAsync(gptr, 0, GRIDN*sizeof(float));

    dim3 pg((PPC/2 + 255)/256, 3);
    point_kernel<<<pg,256>>>(inputs, goals, backgrounds, W1,b1,W2,b2,W3,b3);

    conv_stack_kernel<<<128,384>>>(conv1_w, convs_w, bn1_g, bn1_b,
                                   bns_g, bns_b, out);
}

// round 13
// speedup vs baseline: 5.2647x; 5.2647x over previous
#include <cuda_runtime.h>
#include <math.h>

#define G     15
#define NB    4
#define NPTS  300000
#define PPC   (NB*NPTS)

// padded grid: [B][12][19 planes][19 rows][24 cols]
#define PLANE 456
#define CSTR  8672
#define BSTR  (12*CSTR)
#define GRIDN (NB*BSTR)

typedef unsigned long long ull;

__device__ float  g_grid[GRIDN];
__device__ float  g_bufA[NB*8*512];
__device__ float  g_bufB[NB*8*512];
__device__ float2 g_slots0[128];
__device__ float2 g_slots1[128];
__device__ unsigned g_flags[128];
__device__ unsigned g_phasev = 0;

// ---------------- helpers ---------------------------------------------------
__device__ __forceinline__ ull pack2(float lo, float hi){
    ull r; asm("mov.b64 %0, {%1,%2};" : "=l"(r) : "f"(lo), "f"(hi)); return r;
}
__device__ __forceinline__ void unpack2(ull v, float& lo, float& hi){
    asm("mov.b64 {%0,%1}, %2;" : "=f"(lo), "=f"(hi) : "l"(v));
}
__device__ __forceinline__ ull fma2(ull a, ull b, ull c){
    ull d; asm("fma.rn.f32x2 %0, %1, %2, %3;" : "=l"(d) : "l"(a), "l"(b), "l"(c)); return d;
}
__device__ __forceinline__ float eluf(float x){ return x > 0.f ? x : (__expf(x)-1.f); }
__device__ __forceinline__ ull elu2(ull v){
    float lo, hi; unpack2(v, lo, hi);
    return pack2(eluf(lo), eluf(hi));
}

// flag-based grid barrier (block0 parallel detect + phase release; monotonic)
__device__ __forceinline__ void gridBar(int t, int bid){
    __shared__ unsigned sMy;
    __syncthreads();
    __threadfence();
    if (t==0) sMy = *((volatile unsigned*)&g_phasev);
    __syncthreads();
    unsigned nxt = sMy + 1u;
    if (bid == 0){
        if (t < 127){
            while (((volatile unsigned*)g_flags)[t+1] != nxt) { }
        }
        __syncthreads();
        __threadfence();
        if (t==0) *((volatile unsigned*)&g_phasev) = nxt;
    } else {
        if (t==0){
            ((volatile unsigned*)g_flags)[bid] = nxt;
            while (*((volatile unsigned*)&g_phasev) != nxt) { }
        }
    }
    __syncthreads();
    __threadfence();
}

// two-value reduction over 384 threads (12 warps)
__device__ __forceinline__ float2 blockRed2(float a, float b, float* sm, int t){
    #pragma unroll
    for (int o=16;o;o>>=1){
        a += __shfl_xor_sync(0xffffffffu, a, o);
        b += __shfl_xor_sync(0xffffffffu, b, o);
    }
    if ((t&31)==0){ sm[(t>>5)*2]=a; sm[(t>>5)*2+1]=b; }
    __syncthreads();
    float2 r; r.x=0.f; r.y=0.f;
    #pragma unroll
    for (int wq=0;wq<12;wq++){ r.x += sm[wq*2]; r.y += sm[wq*2+1]; }
    return r;
}

// parallel BN-stats: 128 threads each read one slot; 16-lane shuffle reduce.
// lane groups are 16-aligned within warps -> xor offsets 8,4,2,1 stay in-group.
__device__ __forceinline__ void bnStats(const float2* slots,
                                        const float* gin, const float* bin,
                                        float* sSc, float* sSh, int t)
{
    if (t < 128){
        int ic = t>>4, q = t&15;
        float2 p = *(const float2*)&slots[ic*16+q];
        float sx = p.x, sy = p.y;
        #pragma unroll
        for (int o=8;o;o>>=1){
            sx += __shfl_xor_sync(0xffffffffu, sx, o);
            sy += __shfl_xor_sync(0xffffffffu, sy, o);
        }
        if (q == 0){
            float m  = sx*(1.f/2048.f);
            float vr = sy*(1.f/2048.f) - m*m;
            float sc = gin[ic]*rsqrtf(vr + 1e-5f);
            sSc[ic]=sc; sSh[ic]=bin[ic]-m*sc;
        }
    }
}

// ---------------- point stage: 1 pt/thread, channel-pair packed f32x2 -------
__device__ __forceinline__ void disty6(float px, float py, float pz,
                                       float f[6], int& cellpad)
{
    const float CLIPHI = 15.0f - 1e-4f;
    float cx = floorf(fminf(fmaxf(px,0.f), CLIPHI));
    float cy = floorf(fminf(fmaxf(py,0.f), CLIPHI));
    float cz = floorf(fminf(fmaxf(pz,0.f), CLIPHI));
    float ocx = px-cx-0.5f, ocy = py-cy-0.5f, ocz = pz-cz-0.5f;
    float lx = ocx+0.5f, ly = ocy+0.5f, lz = ocz+0.5f;
    float ux = ocx-0.5f, uy = ocy-0.5f, uz = ocz-0.5f;
    f[0]=ocx; f[1]=ocy; f[2]=ocz;
    f[3] = sqrtf(ocx*ocx+ocy*ocy+ocz*ocz);
    f[4] = sqrtf(lx*lx+ly*ly+lz*lz);
    f[5] = sqrtf(ux*ux+uy*uy+uz*uz);
    cellpad = ((int)cx+2)*PLANE + ((int)cy+2)*24 + ((int)cz+2);
}

__global__ void __launch_bounds__(256,3)
point_kernel(const float* __restrict__ P0, const float* __restrict__ P1,
             const float* __restrict__ P2,
             const float* __restrict__ W1, const float* __restrict__ B1,
             const float* __restrict__ W2, const float* __restrict__ B2,
             const float* __restrict__ W3, const float* __restrict__ B3)
{
    __shared__ __align__(16) ull pW1[48], pW2[128], pW3[32];
    __shared__ ull pb1[8], pb2[8], pb3[2];
    int t = threadIdx.x;

    if (t < 48){
        int k = t>>3, jp = t&7, j0 = 2*jp, j1 = 2*jp+1;
        float w0, w1v;
        if (k < 3){
            w0  = W1[k*16+j0]+W1[(k+3)*16+j0]+W1[(k+6)*16+j0];
            w1v = W1[k*16+j1]+W1[(k+3)*16+j1]+W1[(k+6)*16+j1];
        } else {
            w0  = W1[(k+6)*16+j0];
            w1v = W1[(k+6)*16+j1];
        }
        pW1[k*8+jp] = pack2(w0, w1v);
    }
    if (t < 8){
        int j0 = 2*t, j1 = 2*t+1;
        float be0 = B1[j0] + 0.5f*((W1[3*16+j0]+W1[4*16+j0]+W1[5*16+j0])
                                 - (W1[6*16+j0]+W1[7*16+j0]+W1[8*16+j0]));
        float be1 = B1[j1] + 0.5f*((W1[3*16+j1]+W1[4*16+j1]+W1[5*16+j1])
                                 - (W1[6*16+j1]+W1[7*16+j1]+W1[8*16+j1]));
        pb1[t] = pack2(be0, be1);
        pb2[t] = pack2(B2[j0], B2[j1]);
    }
    if (t < 128){
        int k = t>>3, jp = t&7;
        pW2[k*8+jp] = pack2(W2[k*16+2*jp], W2[k*16+2*jp+1]);
    }
    if (t < 32){
        int k = t>>1, jp = t&1;
        pW3[k*2+jp] = pack2(W3[k*4+2*jp], W3[k*4+2*jp+1]);
    }
    if (t < 2) pb3[t] = pack2(B3[2*t], B3[2*t+1]);
    __syncthreads();

    const float* pts = (blockIdx.y==0) ? P0 : (blockIdx.y==1 ? P1 : P2);
    int chan = blockIdx.y*4;

    long pid = (long)blockIdx.x*256 + t;
    if (pid >= PPC) return;

    float px = pts[pid*3], py = pts[pid*3+1], pz = pts[pid*3+2];
    float fa[6]; int cell;
    disty6(px, py, pz, fa, cell);

    // layer 1: 6 eff inputs -> 16 (8 pairs), ELU
    ull h[8];
    {
        ull xx0=pack2(fa[0],fa[0]), xx1=pack2(fa[1],fa[1]), xx2=pack2(fa[2],fa[2]);
        ull xx3=pack2(fa[3],fa[3]), xx4=pack2(fa[4],fa[4]), xx5=pack2(fa[5],fa[5]);
        #pragma unroll
        for (int jp=0;jp<8;jp++){
            ull a = pb1[jp];
            a = fma2(xx0, pW1[0*8+jp], a);
            a = fma2(xx1, pW1[1*8+jp], a);
            a = fma2(xx2, pW1[2*8+jp], a);
            a = fma2(xx3, pW1[3*8+jp], a);
            a = fma2(xx4, pW1[4*8+jp], a);
            a = fma2(xx5, pW1[5*8+jp], a);
            h[jp] = elu2(a);
        }
    }

    // broadcast-pack h -> 16 {v,v}
    ull hh[16];
    #pragma unroll
    for (int jp=0;jp<8;jp++){
        float s0, s1; unpack2(h[jp], s0, s1);
        hh[2*jp]   = pack2(s0, s0);
        hh[2*jp+1] = pack2(s1, s1);
    }

    // layer 2: 16 -> 16 (8 pairs), ELU
    ull g[8];
    #pragma unroll
    for (int jp=0;jp<8;jp++){
        ull a = pb2[jp];
        #pragma unroll
        for (int k=0;k<16;k++) a = fma2(hh[k], pW2[k*8+jp], a);
        g[jp] = elu2(a);
    }
    #pragma unroll
    for (int jp=0;jp<8;jp++){
        float s0, s1; unpack2(g[jp], s0, s1);
        hh[2*jp]   = pack2(s0, s0);
        hh[2*jp+1] = pack2(s1, s1);
    }

    // layer 3: 16 -> 4 (2 pairs) + scatter-max
    int b = (int)(pid / NPTS);
    int base = b*BSTR + chan*CSTR + cell;
    #pragma unroll
    for (int jp=0;jp<2;jp++){
        ull a = pb3[jp];
        #pragma unroll
        for (int k=0;k<16;k++) a = fma2(hh[k], pW3[k*2+jp], a);
        float v0, v1; unpack2(a, v0, v1);
        if (v0 > 0.f) atomicMax((int*)&g_grid[base + (2*jp  )*CSTR], __float_as_int(v0));
        if (v1 > 0.f) atomicMax((int*)&g_grid[base + (2*jp+1)*CSTR], __float_as_int(v1));
    }
}

// ---------------- fused conv stack: 384 threads/block -----------------------
// grid 128 = (oc8, b4, odp4); thread = (cic, odl, oh, owh) computes 4 ow.
__global__ void __launch_bounds__(384,1)
conv_stack_kernel(const float* __restrict__ w1,
                  const float* __restrict__ wS,
                  const float* __restrict__ bn1_g, const float* __restrict__ bn1_b,
                  const float* __restrict__ bns_g, const float* __restrict__ bns_b,
                  float* __restrict__ outp)
{
    __shared__ __align__(16) float sIn[6912];    // [8 ic][6 dd][12 h][12 w]
    __shared__ __align__(16) float wsm[1600];    // [8 ic][5 kd][5 kh][8 kw-pad]
    __shared__ __align__(16) float sAcc[1536];   // [<=12 ic][128 out]
    __shared__ float sSc[8], sSh[8], sred[24];

    int bid = blockIdx.x;
    int oc = bid & 7, b = (bid>>3) & 3, odp = bid>>5;
    int t = threadIdx.x;
    int owh  = t&1;
    int coh  = (t>>1)&7;
    int codl = (t>>4)&1;
    int cic  = t>>5;
    int obase = b*4096 + oc*512 + odp*128;

    { // zero sIn once (halo cells identical every layer)
        float4 z4 = make_float4(0.f,0.f,0.f,0.f);
        for (int i=t;i<1728;i+=384) ((float4*)sIn)[i] = z4;
    }

    // ================= conv1: 12->8, k5, s2, p2, direct-from-L2 =============
    float accL;
    {
        float a[4] = {0.f,0.f,0.f,0.f};
        const float* gch = g_grid + (b*12+cic)*CSTR;
        const float* wp0 = w1 + (oc*12+cic)*125;
        int od = odp*2 + codl;
        #pragma unroll
        for (int kd=0;kd<5;kd++){
            #pragma unroll
            for (int kh=0;kh<5;kh++){
                const float* row = gch + (2*od+kd)*PLANE + (2*coh+kh)*24 + 8*owh;
                float4 r0 = *(const float4*)(row);
                float4 r1 = *(const float4*)(row+4);
                float4 r2 = *(const float4*)(row+8);
                float rr[12] = {r0.x,r0.y,r0.z,r0.w, r1.x,r1.y,r1.z,r1.w,
                                r2.x,r2.y,r2.z,r2.w};
                const float* wp = wp0 + kd*25 + kh*5;
                float wk0=__ldg(wp), wk1=__ldg(wp+1), wk2=__ldg(wp+2),
                      wk3=__ldg(wp+3), wk4=__ldg(wp+4);
                #pragma unroll
                for (int o=0;o<4;o++){
                    a[o] += rr[2*o+0]*wk0;
                    a[o] += rr[2*o+1]*wk1;
                    a[o] += rr[2*o+2]*wk2;
                    a[o] += rr[2*o+3]*wk3;
                    a[o] += rr[2*o+4]*wk4;
                }
            }
        }
        int oidx = codl*64 + coh*8 + owh*4;
        #pragma unroll
        for (int o=0;o<4;o++) sAcc[cic*128 + oidx + o] = a[o];
        __syncthreads();

        float s = 0.f;
        if (t < 128){
            #pragma unroll
            for (int ic=0;ic<12;ic++) s += sAcc[ic*128 + t];
            __stcg(&g_bufA[obase + t], s);
        }
        accL = s;
        float2 r = blockRed2(t<128 ? s : 0.f, t<128 ? s*s : 0.f, sred, t);
        if (t==0){ g_slots0[oc*16 + b*4 + odp] = r; }
    }
    gridBar(t, bid);

    // ================= 6x (input BN+ELU -> conv 8->8 k5 p2) =================
    for (int L=0; L<6; L++){
        int dir = L & 1;
        const float*  rin  = dir ? g_bufB   : g_bufA;
        float*        rout = dir ? g_bufA   : g_bufB;
        const float2* sinp = dir ? g_slots1 : g_slots0;
        float2*       sout = dir ? g_slots0 : g_slots1;
        const float*  gin  = (L==0) ? bn1_g : (bns_g + (L-1)*8);
        const float*  bin  = (L==0) ? bn1_b : (bns_b + (L-1)*8);
        const float*  w    = wS + L*8000;

        bnStats(sinp, gin, bin, sSc, sSh, t);
        for (int i=t;i<1000;i+=384){
            int ic=i/125, r=i%125, kd=r/25, kh=(r%25)/5, kw=r%5;
            wsm[((ic*5+kd)*5+kh)*8 + kw] = w[oc*1000 + i];
        }
        __syncthreads();

        // batched interior fill (768 float4 items over 384 threads)
        {
            float4 vv[2]; bool ok[2]; int di[2];
            #pragma unroll
            for (int u=0;u<2;u++){
                int i = t + u*384;
                int half = i&1, h = (i>>1)&7, dd = (i>>4)%6, ic = i/96;
                int id = odp*2 - 2 + dd;
                ok[u] = (unsigned)id < 8u;
                di[u] = ic*864 + dd*144 + (h+2)*12 + 2 + half*4;
                if (ok[u])
                    vv[u] = __ldcg((const float4*)(rin + b*4096 + ic*512 + id*64 + h*8 + half*4));
            }
            #pragma unroll
            for (int u=0;u<2;u++){
                if (ok[u]){
                    int i = t + u*384;
                    int ic = i/96;
                    float sc = sSc[ic], sh = sSh[ic];
                    float* d = sIn + di[u];
                    d[0]=eluf(vv[u].x*sc+sh); d[1]=eluf(vv[u].y*sc+sh);
                    d[2]=eluf(vv[u].z*sc+sh); d[3]=eluf(vv[u].w*sc+sh);
                }
            }
        }
        __syncthreads();

        float a[4] = {0.f,0.f,0.f,0.f};
        if (cic < 8){
            const float* cb = sIn + cic*864;
            const float* wb = wsm + cic*200;
            #pragma unroll
            for (int kd=0;kd<5;kd++){
                #pragma unroll
                for (int kh=0;kh<5;kh++){
                    const float* row = cb + (codl+kd)*144 + (coh+kh)*12 + owh*4;
                    float4 r0 = *(const float4*)(row);
                    float4 r1 = *(const float4*)(row+4);
                    float rr[8] = {r0.x,r0.y,r0.z,r0.w, r1.x,r1.y,r1.z,r1.w};
                    const float* wp = wb + (kd*5+kh)*8;
                    float4 wv = *(const float4*)wp;
                    float wk4 = wp[4];
                    #pragma unroll
                    for (int o=0;o<4;o++){
                        a[o] += rr[o+0]*wv.x;
                        a[o] += rr[o+1]*wv.y;
                        a[o] += rr[o+2]*wv.z;
                        a[o] += rr[o+3]*wv.w;
                        a[o] += rr[o+4]*wk4;
                    }
                }
            }
            int oidx = codl*64 + coh*8 + owh*4;
            #pragma unroll
            for (int o=0;o<4;o++) sAcc[cic*128 + oidx + o] = a[o];
        }
        __syncthreads();

        float s = 0.f;
        if (t < 128){
            #pragma unroll
            for (int ic=0;ic<8;ic++) s += sAcc[ic*128 + t];
            __stcg(&rout[obase + t], s);
        }
        accL = s;
        float2 r = blockRed2(t<128 ? s : 0.f, t<128 ? s*s : 0.f, sred, t);
        if (t==0){ sout[oc*16 + b*4 + odp] = r; }
        gridBar(t, bid);
    }

    // ================= final BN+ELU from live accumulator ===================
    if (t < 128){
        int q = t&15;
        float2 p = *(const float2*)&g_slots0[oc*16+q];
        float sx = p.x, sy = p.y;
        #pragma unroll
        for (int o=8;o;o>>=1){
            sx += __shfl_xor_sync(0xffffffffu, sx, o);
            sy += __shfl_xor_sync(0xffffffffu, sy, o);
        }
        float m  = sx*(1.f/2048.f);
        float vr = sy*(1.f/2048.f) - m*m;
        float sc = bns_g[40+oc]*rsqrtf(vr + 1e-5f);
        float sh = bns_b[40+oc]-m*sc;
        outp[(b*8+oc)*512 + odp*128 + t] = eluf(accL*sc+sh);
    }
}

// ---------------------------------------------------------------------------
extern "C" void kernel_launch(void* const* d_in, const int* in_sizes, int n_in,
                              void* d_out, int out_size)
{
    const float* goals       = (const float*)d_in[0];
    const float* inputs      = (const float*)d_in[1];
    const float* backgrounds = (const float*)d_in[2];
    const float* W1 = (const float*)d_in[3];
    const float* b1 = (const float*)d_in[4];
    const float* W2 = (const float*)d_in[5];
    const float* b2 = (const float*)d_in[6];
    const float* W3 = (const float*)d_in[7];
    const float* b3 = (const float*)d_in[8];
    const float* conv1_w = (const float*)d_in[9];
    const float* bn1_g   = (const float*)d_in[11];
    const float* bn1_b   = (const float*)d_in[12];
    const float* convs_w = (const float*)d_in[13];
    const float* bns_g   = (const float*)d_in[15];
    const float* bns_b   = (const float*)d_in[16];
    float* out = (float*)d_out;

    void* gptr = nullptr;
    cudaGetSymbolAddress(&gptr, g_grid);
    cudaMemsetAsync(gptr, 0, GRIDN*sizeof(float));

    dim3 pg((PPC + 255)/256, 3);
    point_kernel<<<pg,256>>>(inputs, goals, backgrounds, W1,b1,W2,b2,W3,b3);

    conv_stack_kernel<<<128,384>>>(conv1_w, convs_w, bn1_g, bn1_b,
                                   bns_g, bns_b, out);
}

// round 14
// speedup vs baseline: 5.6830x; 1.0795x over previous
#include <cuda_runtime.h>
#include <math.h>

#define G     15
#define NB    4
#define NPTS  300000
#define PPC   (NB*NPTS)

// padded grid: [B][12][19 planes][19 rows][24 cols]
#define PLANE 456
#define CSTR  8672
#define BSTR  (12*CSTR)
#define GRIDN (NB*BSTR)

typedef unsigned long long ull;

__device__ float  g_grid[GRIDN];
__device__ float  g_bufA[NB*8*512];
__device__ float  g_bufB[NB*8*512];
__device__ float2 g_slots0[128];
__device__ float2 g_slots1[128];
__device__ unsigned g_flags[128];
__device__ unsigned g_phasev = 0;

// ---------------- helpers ---------------------------------------------------
__device__ __forceinline__ ull pack2(float lo, float hi){
    ull r; asm("mov.b64 %0, {%1,%2};" : "=l"(r) : "f"(lo), "f"(hi)); return r;
}
__device__ __forceinline__ void unpack2(ull v, float& lo, float& hi){
    asm("mov.b64 {%0,%1}, %2;" : "=f"(lo), "=f"(hi) : "l"(v));
}
__device__ __forceinline__ ull fma2(ull a, ull b, ull c){
    ull d; asm("fma.rn.f32x2 %0, %1, %2, %3;" : "=l"(d) : "l"(a), "l"(b), "l"(c)); return d;
}
__device__ __forceinline__ float eluf(float x){ return x > 0.f ? x : (__expf(x)-1.f); }
__device__ __forceinline__ ull elu2(ull v){
    float lo, hi; unpack2(v, lo, hi);
    return pack2(eluf(lo), eluf(hi));
}

// flag-based grid barrier (block0 parallel detect + phase release; monotonic)
__device__ __forceinline__ void gridBar(int t, int bid){
    __shared__ unsigned sMy;
    __syncthreads();
    __threadfence();
    if (t==0) sMy = *((volatile unsigned*)&g_phasev);
    __syncthreads();
    unsigned nxt = sMy + 1u;
    if (bid == 0){
        if (t < 127){
            while (((volatile unsigned*)g_flags)[t+1] != nxt) { }
        }
        __syncthreads();
        __threadfence();
        if (t==0) *((volatile unsigned*)&g_phasev) = nxt;
    } else {
        if (t==0){
            ((volatile unsigned*)g_flags)[bid] = nxt;
            while (*((volatile unsigned*)&g_phasev) != nxt) { }
        }
    }
    __syncthreads();
    __threadfence();
}

// two-value reduction over 384 threads (12 warps)
__device__ __forceinline__ float2 blockRed2(float a, float b, float* sm, int t){
    #pragma unroll
    for (int o=16;o;o>>=1){
        a += __shfl_xor_sync(0xffffffffu, a, o);
        b += __shfl_xor_sync(0xffffffffu, b, o);
    }
    if ((t&31)==0){ sm[(t>>5)*2]=a; sm[(t>>5)*2+1]=b; }
    __syncthreads();
    float2 r; r.x=0.f; r.y=0.f;
    #pragma unroll
    for (int wq=0;wq<12;wq++){ r.x += sm[wq*2]; r.y += sm[wq*2+1]; }
    return r;
}

// parallel BN-stats: 128 threads each read one slot; 16-lane shuffle reduce
__device__ __forceinline__ void bnStats(const float2* slots,
                                        const float* gin, const float* bin,
                                        float* sSc, float* sSh, int t)
{
    if (t < 128){
        int ic = t>>4, q = t&15;
        float2 p = *(const float2*)&slots[ic*16+q];
        float sx = p.x, sy = p.y;
        #pragma unroll
        for (int o=8;o;o>>=1){
            sx += __shfl_xor_sync(0xffffffffu, sx, o);
            sy += __shfl_xor_sync(0xffffffffu, sy, o);
        }
        if (q == 0){
            float m  = sx*(1.f/2048.f);
            float vr = sy*(1.f/2048.f) - m*m;
            float sc = gin[ic]*rsqrtf(vr + 1e-5f);
            sSc[ic]=sc; sSh[ic]=bin[ic]-m*sc;
        }
    }
}

// ---------------- point stage: 2 pts/thread, k-outer, channel-pair weights --
__device__ __forceinline__ void disty6(float px, float py, float pz,
                                       float f[6], int& cellpad)
{
    const float CLIPHI = 15.0f - 1e-4f;
    float cx = floorf(fminf(fmaxf(px,0.f), CLIPHI));
    float cy = floorf(fminf(fmaxf(py,0.f), CLIPHI));
    float cz = floorf(fminf(fmaxf(pz,0.f), CLIPHI));
    float ocx = px-cx-0.5f, ocy = py-cy-0.5f, ocz = pz-cz-0.5f;
    float lx = ocx+0.5f, ly = ocy+0.5f, lz = ocz+0.5f;
    float ux = ocx-0.5f, uy = ocy-0.5f, uz = ocz-0.5f;
    f[0]=ocx; f[1]=ocy; f[2]=ocz;
    f[3] = sqrtf(ocx*ocx+ocy*ocy+ocz*ocz);
    f[4] = sqrtf(lx*lx+ly*ly+lz*lz);
    f[5] = sqrtf(ux*ux+uy*uy+uz*uz);
    cellpad = ((int)cx+2)*PLANE + ((int)cy+2)*24 + ((int)cz+2);
}

__global__ void __launch_bounds__(256,2)
point_kernel(const float* __restrict__ P0, const float* __restrict__ P1,
             const float* __restrict__ P2,
             const float* __restrict__ W1, const float* __restrict__ B1,
             const float* __restrict__ W2, const float* __restrict__ B2,
             const float* __restrict__ W3, const float* __restrict__ B3)
{
    __shared__ __align__(16) ull pW1[48], pW2[128], pW3[32];
    __shared__ ull pb1[8], pb2[8], pb3[2];
    int t = threadIdx.x;

    if (t < 48){
        int k = t>>3, jp = t&7, j0 = 2*jp, j1 = 2*jp+1;
        float w0, w1v;
        if (k < 3){
            w0  = W1[k*16+j0]+W1[(k+3)*16+j0]+W1[(k+6)*16+j0];
            w1v = W1[k*16+j1]+W1[(k+3)*16+j1]+W1[(k+6)*16+j1];
        } else {
            w0  = W1[(k+6)*16+j0];
            w1v = W1[(k+6)*16+j1];
        }
        pW1[k*8+jp] = pack2(w0, w1v);
    }
    if (t < 8){
        int j0 = 2*t, j1 = 2*t+1;
        float be0 = B1[j0] + 0.5f*((W1[3*16+j0]+W1[4*16+j0]+W1[5*16+j0])
                                 - (W1[6*16+j0]+W1[7*16+j0]+W1[8*16+j0]));
        float be1 = B1[j1] + 0.5f*((W1[3*16+j1]+W1[4*16+j1]+W1[5*16+j1])
                                 - (W1[6*16+j1]+W1[7*16+j1]+W1[8*16+j1]));
        pb1[t] = pack2(be0, be1);
        pb2[t] = pack2(B2[j0], B2[j1]);
    }
    if (t < 128){
        int k = t>>3, jp = t&7;
        pW2[k*8+jp] = pack2(W2[k*16+2*jp], W2[k*16+2*jp+1]);
    }
    if (t < 32){
        int k = t>>1, jp = t&1;
        pW3[k*2+jp] = pack2(W3[k*4+2*jp], W3[k*4+2*jp+1]);
    }
    if (t < 2) pb3[t] = pack2(B3[2*t], B3[2*t+1]);
    __syncthreads();

    const float* pts = (blockIdx.y==0) ? P0 : (blockIdx.y==1 ? P1 : P2);
    int chan = blockIdx.y*4;

    long p0 = ((long)blockIdx.x*256 + t)*2;
    if (p0 >= PPC) return;

    const float2* v = (const float2*)(pts + p0*3);
    float2 q0=v[0], q1=v[1], q2=v[2];
    int b = (int)(p0 / NPTS);

    float fA[6], fB[6]; int cA, cB;
    disty6(q0.x, q0.y, q1.x, fA, cA);
    disty6(q1.y, q2.x, q2.y, fB, cB);

    // ---- layer 1 (k-outer): 6 eff inputs -> 16 ch (8 pairs) x 2 pts --------
    ull aA[8], aB[8];
    #pragma unroll
    for (int jp=0;jp<8;jp++){ aA[jp]=pb1[jp]; aB[jp]=pb1[jp]; }
    #pragma unroll
    for (int k=0;k<6;k++){
        ull xA = pack2(fA[k], fA[k]);
        ull xB = pack2(fB[k], fB[k]);
        #pragma unroll
        for (int jp=0;jp<8;jp++){
            ull w = pW1[k*8+jp];
            aA[jp] = fma2(xA, w, aA[jp]);
            aB[jp] = fma2(xB, w, aB[jp]);
        }
    }
    ull hA[8], hB[8];
    #pragma unroll
    for (int jp=0;jp<8;jp++){ hA[jp]=elu2(aA[jp]); hB[jp]=elu2(aB[jp]); }

    // ---- layer 2 (k-outer): 16 -> 16 (8 pairs) x 2 pts ---------------------
    #pragma unroll
    for (int jp=0;jp<8;jp++){ aA[jp]=pb2[jp]; aB[jp]=pb2[jp]; }
    #pragma unroll
    for (int k=0;k<16;k++){
        float sA0, sA1, sB0, sB1;
        unpack2(hA[k>>1], sA0, sA1);
        unpack2(hB[k>>1], sB0, sB1);
        float vAx = (k&1) ? sA1 : sA0;
        float vBx = (k&1) ? sB1 : sB0;
        ull xA = pack2(vAx, vAx);
        ull xB = pack2(vBx, vBx);
        #pragma unroll
        for (int jp=0;jp<8;jp++){
            ull w = pW2[k*8+jp];
            aA[jp] = fma2(xA, w, aA[jp]);
            aB[jp] = fma2(xB, w, aB[jp]);
        }
    }
    #pragma unroll
    for (int jp=0;jp<8;jp++){ hA[jp]=elu2(aA[jp]); hB[jp]=elu2(aB[jp]); }

    // ---- layer 3 (k-outer): 16 -> 4 (2 pairs) x 2 pts + scatter-max --------
    ull oA[2], oB[2];
    oA[0]=pb3[0]; oA[1]=pb3[1]; oB[0]=pb3[0]; oB[1]=pb3[1];
    #pragma unroll
    for (int k=0;k<16;k++){
        float sA0, sA1, sB0, sB1;
        unpack2(hA[k>>1], sA0, sA1);
        unpack2(hB[k>>1], sB0, sB1);
        float vAx = (k&1) ? sA1 : sA0;
        float vBx = (k&1) ? sB1 : sB0;
        ull xA = pack2(vAx, vAx);
        ull xB = pack2(vBx, vBx);
        #pragma unroll
        for (int jp=0;jp<2;jp++){
            ull w = pW3[k*2+jp];
            oA[jp] = fma2(xA, w, oA[jp]);
            oB[jp] = fma2(xB, w, oB[jp]);
        }
    }
    int baseA = b*BSTR + chan*CSTR + cA;
    int baseB = b*BSTR + chan*CSTR + cB;
    #pragma unroll
    for (int jp=0;jp<2;jp++){
        float v0, v1; unpack2(oA[jp], v0, v1);
        if (v0 > 0.f) atomicMax((int*)&g_grid[baseA + (2*jp  )*CSTR], __float_as_int(v0));
        if (v1 > 0.f) atomicMax((int*)&g_grid[baseA + (2*jp+1)*CSTR], __float_as_int(v1));
        float u0, u1; unpack2(oB[jp], u0, u1);
        if (u0 > 0.f) atomicMax((int*)&g_grid[baseB + (2*jp  )*CSTR], __float_as_int(u0));
        if (u1 > 0.f) atomicMax((int*)&g_grid[baseB + (2*jp+1)*CSTR], __float_as_int(u1));
    }
}

// ---------------- fused conv stack: 384 threads/block -----------------------
__global__ void __launch_bounds__(384,1)
conv_stack_kernel(const float* __restrict__ w1,
                  const float* __restrict__ wS,
                  const float* __restrict__ bn1_g, const float* __restrict__ bn1_b,
                  const float* __restrict__ bns_g, const float* __restrict__ bns_b,
                  float* __restrict__ outp)
{
    __shared__ __align__(16) float sIn[6912];
    __shared__ __align__(16) float wsm[1600];
    __shared__ __align__(16) float sAcc[1536];
    __shared__ float sSc[8], sSh[8], sred[24];

    int bid = blockIdx.x;
    int oc = bid & 7, b = (bid>>3) & 3, odp = bid>>5;
    int t = threadIdx.x;
    int owh  = t&1;
    int coh  = (t>>1)&7;
    int codl = (t>>4)&1;
    int cic  = t>>5;
    int obase = b*4096 + oc*512 + odp*128;

    {
        float4 z4 = make_float4(0.f,0.f,0.f,0.f);
        for (int i=t;i<1728;i+=384) ((float4*)sIn)[i] = z4;
    }

    // ================= conv1: 12->8, k5, s2, p2, direct-from-L2 =============
    float accL;
    {
        float a[4] = {0.f,0.f,0.f,0.f};
        const float* gch = g_grid + (b*12+cic)*CSTR;
        const float* wp0 = w1 + (oc*12+cic)*125;
        int od = odp*2 + codl;
        #pragma unroll
        for (int kd=0;kd<5;kd++){
            #pragma unroll
            for (int kh=0;kh<5;kh++){
                const float* row = gch + (2*od+kd)*PLANE + (2*coh+kh)*24 + 8*owh;
                float4 r0 = *(const float4*)(row);
                float4 r1 = *(const float4*)(row+4);
                float4 r2 = *(const float4*)(row+8);
                float rr[12] = {r0.x,r0.y,r0.z,r0.w, r1.x,r1.y,r1.z,r1.w,
                                r2.x,r2.y,r2.z,r2.w};
                const float* wp = wp0 + kd*25 + kh*5;
                float wk0=__ldg(wp), wk1=__ldg(wp+1), wk2=__ldg(wp+2),
                      wk3=__ldg(wp+3), wk4=__ldg(wp+4);
                #pragma unroll
                for (int o=0;o<4;o++){
                    a[o] += rr[2*o+0]*wk0;
                    a[o] += rr[2*o+1]*wk1;
                    a[o] += rr[2*o+2]*wk2;
                    a[o] += rr[2*o+3]*wk3;
                    a[o] += rr[2*o+4]*wk4;
                }
            }
        }
        int oidx = codl*64 + coh*8 + owh*4;
        #pragma unroll
        for (int o=0;o<4;o++) sAcc[cic*128 + oidx + o] = a[o];
        __syncthreads();

        float s = 0.f;
        if (t < 128){
            #pragma unroll
            for (int ic=0;ic<12;ic++) s += sAcc[ic*128 + t];
            __stcg(&g_bufA[obase + t], s);
        }
        accL = s;
        float2 r = blockRed2(t<128 ? s : 0.f, t<128 ? s*s : 0.f, sred, t);
        if (t==0){ g_slots0[oc*16 + b*4 + odp] = r; }
    }
    gridBar(t, bid);

    // ================= 6x (input BN+ELU -> conv 8->8 k5 p2) =================
    for (int L=0; L<6; L++){
        int dir = L & 1;
        const float*  rin  = dir ? g_bufB   : g_bufA;
        float*        rout = dir ? g_bufA   : g_bufB;
        const float2* sinp = dir ? g_slots1 : g_slots0;
        float2*       sout = dir ? g_slots0 : g_slots1;
        const float*  gin  = (L==0) ? bn1_g : (bns_g + (L-1)*8);
        const float*  bin  = (L==0) ? bn1_b : (bns_b + (L-1)*8);
        const float*  w    = wS + L*8000;

        // issue fill loads FIRST (only depend on gridBar), overlap with stats
        float4 vv[2]; bool ok[2]; int di[2]; int icu[2];
        #pragma unroll
        for (int u=0;u<2;u++){
            int i = t + u*384;
            int half = i&1, h = (i>>1)&7, dd = (i>>4)%6, ic = i/96;
            int id = odp*2 - 2 + dd;
            ok[u]  = (unsigned)id < 8u;
            icu[u] = ic;
            di[u]  = ic*864 + dd*144 + (h+2)*12 + 2 + half*4;
            if (ok[u])
                vv[u] = __ldcg((const float4*)(rin + b*4096 + ic*512 + id*64 + h*8 + half*4));
        }
        for (int i=t;i<1000;i+=384){
            int ic=i/125, r=i%125, kd=r/25, kh=(r%25)/5, kw=r%5;
            wsm[((ic*5+kd)*5+kh)*8 + kw] = w[oc*1000 + i];
        }
        bnStats(sinp, gin, bin, sSc, sSh, t);
        __syncthreads();

        #pragma unroll
        for (int u=0;u<2;u++){
            if (ok[u]){
                float sc = sSc[icu[u]], sh = sSh[icu[u]];
                float* d = sIn + di[u];
                d[0]=eluf(vv[u].x*sc+sh); d[1]=eluf(vv[u].y*sc+sh);
                d[2]=eluf(vv[u].z*sc+sh); d[3]=eluf(vv[u].w*sc+sh);
            }
        }
        __syncthreads();

        float a[4] = {0.f,0.f,0.f,0.f};
        if (cic < 8){
            const float* cb = sIn + cic*864;
            const float* wb = wsm + cic*200;
            #pragma unroll
            for (int kd=0;kd<5;kd++){
                #pragma unroll
                for (int kh=0;kh<5;kh++){
                    const float* row = cb + (codl+kd)*144 + (coh+kh)*12 + owh*4;
                    float4 r0 = *(const float4*)(row);
                    float4 r1 = *(const float4*)(row+4);
                    float rr[8] = {r0.x,r0.y,r0.z,r0.w, r1.x,r1.y,r1.z,r1.w};
                    const float* wp = wb + (kd*5+kh)*8;
                    float4 wv = *(const float4*)wp;
                    float wk4 = wp[4];
                    #pragma unroll
                    for (int o=0;o<4;o++){
                        a[o] += rr[o+0]*wv.x;
                        a[o] += rr[o+1]*wv.y;
                        a[o] += rr[o+2]*wv.z;
                        a[o] += rr[o+3]*wv.w;
                        a[o] += rr[o+4]*wk4;
                    }
                }
            }
            int oidx = codl*64 + coh*8 + owh*4;
            #pragma unroll
            for (int o=0;o<4;o++) sAcc[cic*128 + oidx + o] = a[o];
        }
        __syncthreads();

        float s = 0.f;
        if (t < 128){
            #pragma unroll
            for (int ic=0;ic<8;ic++) s += sAcc[ic*128 + t];
            __stcg(&rout[obase + t], s);
        }
        accL = s;
        float2 r = blockRed2(t<128 ? s : 0.f, t<128 ? s*s : 0.f, sred, t);
        if (t==0){ sout[oc*16 + b*4 + odp] = r; }
        gridBar(t, bid);
    }

    // ================= final BN+ELU from live accumulator ===================
    if (t < 128){
        int q = t&15;
        float2 p = *(const float2*)&g_slots0[oc*16+q];
        float sx = p.x, sy = p.y;
        #pragma unroll
        for (int o=8;o;o>>=1){
            sx += __shfl_xor_sync(0xffffffffu, sx, o);
            sy += __shfl_xor_sync(0xffffffffu, sy, o);
        }
        float m  = sx*(1.f/2048.f);
        float vr = sy*(1.f/2048.f) - m*m;
        float sc = bns_g[40+oc]*rsqrtf(vr + 1e-5f);
        float sh = bns_b[40+oc]-m*sc;
        outp[(b*8+oc)*512 + odp*128 + t] = eluf(accL*sc+sh);
    }
}

// ---------------------------------------------------------------------------
extern "C" void kernel_launch(void* const* d_in, const int* in_sizes, int n_in,
                              void* d_out, int out_size)
{
    const float* goals       = (const float*)d_in[0];
    const float* inputs      = (const float*)d_in[1];
    const float* backgrounds = (const float*)d_in[2];
    const float* W1 = (const float*)d_in[3];
    const float* b1 = (const float*)d_in[4];
    const float* W2 = (const float*)d_in[5];
    const float* b2 = (const float*)d_in[6];
    const float* W3 = (const float*)d_in[7];
    const float* b3 = (const float*)d_in[8];
    const float* conv1_w = (const float*)d_in[9];
    const float* bn1_g   = (const float*)d_in[11];
    const float* bn1_b   = (const float*)d_in[12];
    const float* convs_w = (const float*)d_in[13];
    const float* bns_g   = (const float*)d_in[15];
    const float* bns_b   = (const float*)d_in[16];
    float* out = (float*)d_out;

    void* gptr = nullptr;
    cudaGetSymbolAddress(&gptr, g_grid);
    cudaMemsetAsync(gptr, 0, GRIDN*sizeof(float));

    dim3 pg((PPC/2 + 255)/256, 3);
    point_kernel<<<pg,256>>>(inputs, goals, backgrounds, W1,b1,W2,b2,W3,b3);

    conv_stack_kernel<<<128,384>>>(conv1_w, convs_w, bn1_g, bn1_b,
                                   bns_g, bns_b, out);
}